// round 1
// baseline (speedup 1.0000x reference)
#include <cuda_runtime.h>
#include <math.h>
#include <stdint.h>

#define BATCH 4
#define LSEQ  2048
#define DMOD  1024
#define DST   16
#define KCONV 4
#define DINN  2048
#define MROWS (BATCH*LSEQ)   /* 8192 */

// ---------------- scratch (device globals: allocation-free rule) ----------
__device__ float g_xr[(size_t)MROWS * (2*DINN)];  // in_proj output (xi | res)
__device__ float g_xs[(size_t)MROWS * DINN];      // conv+silu output
__device__ float g_bc[(size_t)MROWS * 32];        // B|C projections
__device__ float g_hs[(size_t)MROWS * DST];       // scan states
__device__ float g_At[16*16*16];                  // exp(dtv[j]*A) table
__device__ float g_Wred[DMOD*DST];                // folded W_out for tiled-hs term

// ---------------- prep: At table --------------------------------------------
__global__ void prep_at(const float* __restrict__ dt, const float* __restrict__ A,
                        float* __restrict__ At) {
    int t = blockIdx.x * blockDim.x + threadIdx.x;   // 0..4095
    if (t < 4096) {
        int j = t >> 8;      // which dt (l % 16)
        int e = t & 255;     // element of 16x16
        float d = expf(dt[j]);
        At[t] = expf(d * A[e]);
    }
}

// ---------------- prep: Wred[m][s] = sum_r W_out[m, 16r+s] ------------------
__global__ void prep_wred(const float* __restrict__ Wout, float* __restrict__ Wred) {
    int t = blockIdx.x * blockDim.x + threadIdx.x;   // 0..16383
    if (t < DMOD*DST) {
        int m = t >> 4, s = t & 15;
        float sum = 0.f;
        #pragma unroll 8
        for (int r = 0; r < DINN/DST; r++)
            sum += Wout[(size_t)m*DINN + r*DST + s];
        Wred[t] = sum;
    }
}

// ---------------- generic register-tiled SGEMM:  C = A @ B^T + bias ---------
// A: MxK (row stride lda), B: NxK (row stride ldb), C: MxN (row stride ldc)
// Optional fused epilogue: C += hs @ Wred^T (hs: Mx16, Wred: Nx16)
template<int BM,int BN,int BK,int TM,int TN,bool FUSE_HS>
__global__ __launch_bounds__((BM/TM)*(BN/TN))
void gemm_tn(const float* __restrict__ A, int lda,
             const float* __restrict__ B, int ldb,
             const float* __restrict__ bias,
             float* __restrict__ C, int ldc,
             int K,
             const float* __restrict__ hsm,
             const float* __restrict__ Wred)
{
    constexpr int THREADS = (BM/TM)*(BN/TN);
    __shared__ float As[BK][BM+4];
    __shared__ float Bs[BK][BN+4];
    const int tid = threadIdx.x;
    const int tx  = tid % (BN/TN);
    const int ty  = tid / (BN/TN);
    const int m0  = blockIdx.y * BM;
    const int n0  = blockIdx.x * BN;

    float acc[TM][TN];
    #pragma unroll
    for (int i = 0; i < TM; i++)
        #pragma unroll
        for (int j = 0; j < TN; j++) acc[i][j] = 0.f;

    for (int k0 = 0; k0 < K; k0 += BK) {
        for (int idx = tid; idx < BM*(BK/4); idx += THREADS) {
            int r  = idx / (BK/4);
            int cv = idx % (BK/4);
            float4 v = *reinterpret_cast<const float4*>(
                &A[(size_t)(m0+r)*lda + k0 + cv*4]);
            As[cv*4+0][r] = v.x; As[cv*4+1][r] = v.y;
            As[cv*4+2][r] = v.z; As[cv*4+3][r] = v.w;
        }
        for (int idx = tid; idx < BN*(BK/4); idx += THREADS) {
            int r  = idx / (BK/4);
            int cv = idx % (BK/4);
            float4 v = *reinterpret_cast<const float4*>(
                &B[(size_t)(n0+r)*ldb + k0 + cv*4]);
            Bs[cv*4+0][r] = v.x; Bs[cv*4+1][r] = v.y;
            Bs[cv*4+2][r] = v.z; Bs[cv*4+3][r] = v.w;
        }
        __syncthreads();
        #pragma unroll
        for (int k = 0; k < BK; k++) {
            float a[TM], bb[TN];
            #pragma unroll
            for (int i = 0; i < TM; i++) a[i]  = As[k][ty*TM + i];
            #pragma unroll
            for (int j = 0; j < TN; j++) bb[j] = Bs[k][tx*TN + j];
            #pragma unroll
            for (int i = 0; i < TM; i++)
                #pragma unroll
                for (int j = 0; j < TN; j++)
                    acc[i][j] = fmaf(a[i], bb[j], acc[i][j]);
        }
        __syncthreads();
    }

    #pragma unroll
    for (int i = 0; i < TM; i++) {
        int m = m0 + ty*TM + i;
        float hrow[16];
        if (FUSE_HS) {
            #pragma unroll
            for (int s = 0; s < 16; s++) hrow[s] = hsm[(size_t)m*16 + s];
        }
        #pragma unroll
        for (int j = 0; j < TN; j++) {
            int n = n0 + tx*TN + j;
            float v = acc[i][j] + bias[n];
            if (FUSE_HS) {
                const float* wp = &Wred[(size_t)n*16];
                #pragma unroll
                for (int s = 0; s < 16; s++) v = fmaf(hrow[s], wp[s], v);
            }
            C[(size_t)m*ldc + n] = v;
        }
    }
}

// ---------------- depthwise causal conv (K=4) + SiLU ------------------------
__global__ void conv_silu(const float* __restrict__ xr,
                          const float* __restrict__ w,
                          const float* __restrict__ cb,
                          float* __restrict__ xs)
{
    long t = (long)blockIdx.x * blockDim.x + threadIdx.x;  // over MROWS*DINN
    if (t >= (long)MROWS * DINN) return;
    int  c  = (int)(t & (DINN-1));
    long bl = t >> 11;            // b*LSEQ + l
    int  l  = (int)(bl & (LSEQ-1));
    long row0 = bl - l;           // b*LSEQ

    float4 wv = *reinterpret_cast<const float4*>(&w[c*4]);
    float acc = cb[c];
    const float wk[4] = {wv.x, wv.y, wv.z, wv.w};
    #pragma unroll
    for (int k = 0; k < KCONV; k++) {
        int ll = l - (KCONV-1) + k;
        if (ll >= 0)
            acc = fmaf(xr[(size_t)(row0 + ll)*(2*DINN) + c], wk[k], acc);
    }
    float s = 1.f / (1.f + expf(-acc));
    xs[t] = acc * s;
}

// ---------------- sequential nonlinear scan ---------------------------------
// one block per batch, 16 threads (lane i owns h[i]).
// h_new[i] = tanh( sum_j At[l%16][i][j]*h[j] + B[l,i]*h[i] + C[l,i] )
__global__ void scan_kernel(const float* __restrict__ bc,
                            const float* __restrict__ At,
                            float* __restrict__ hs)
{
    const int b = blockIdx.x;
    const int i = threadIdx.x;            // 0..15
    const unsigned mask = 0xffffu;
    __shared__ float sAt[16*16*16];       // 16 KB
    __shared__ float sBC[64*32];          // 8 KB chunk of B|C rows

    for (int t = i; t < 4096/4; t += 16)
        reinterpret_cast<float4*>(sAt)[t] =
            reinterpret_cast<const float4*>(At)[t];

    const float* bcb = bc + (size_t)b*LSEQ*32;
    float*       hsb = hs + (size_t)b*LSEQ*DST;
    float h = 0.f;

    for (int l0 = 0; l0 < LSEQ; l0 += 64) {
        __syncwarp(mask);
        const float4* src = reinterpret_cast<const float4*>(bcb + (size_t)l0*32);
        for (int t = i; t < 64*32/4; t += 16)
            reinterpret_cast<float4*>(sBC)[t] = src[t];
        __syncwarp(mask);
        for (int ll = 0; ll < 64; ll++) {
            int l = l0 + ll;
            float Bv = sBC[ll*32 + i];
            float Cv = sBC[ll*32 + 16 + i];
            const float* Ar = &sAt[((l & 15) << 8) + (i << 4)];
            float a0 = Cv, a1 = 0.f, a2 = 0.f, a3 = Bv * h;
            #pragma unroll
            for (int j = 0; j < 16; j += 4) {
                a0 = fmaf(Ar[j+0], __shfl_sync(mask, h, j+0), a0);
                a1 = fmaf(Ar[j+1], __shfl_sync(mask, h, j+1), a1);
                a2 = fmaf(Ar[j+2], __shfl_sync(mask, h, j+2), a2);
                a3 = fmaf(Ar[j+3], __shfl_sync(mask, h, j+3), a3);
            }
            h = tanhf((a0 + a1) + (a2 + a3));
            hsb[(size_t)l*DST + i] = h;
        }
    }
}

// ---------------- launcher ---------------------------------------------------
extern "C" void kernel_launch(void* const* d_in, const int* in_sizes, int n_in,
                              void* d_out, int out_size)
{
    const float* x      = (const float*)d_in[0];
    const float* W_in   = (const float*)d_in[1];
    const float* b_in   = (const float*)d_in[2];
    const float* conv_w = (const float*)d_in[3];
    const float* conv_b = (const float*)d_in[4];
    const float* W_x    = (const float*)d_in[5];
    const float* b_x    = (const float*)d_in[6];
    const float* dt     = (const float*)d_in[7];
    const float* A      = (const float*)d_in[8];
    /* d_in[9] = D: computed but unused by the reference scan */
    const float* W_out  = (const float*)d_in[10];
    const float* b_out  = (const float*)d_in[11];
    float* out = (float*)d_out;

    float *xr, *xs, *bc, *hsp, *Atp, *Wred;
    cudaGetSymbolAddress((void**)&xr,   g_xr);
    cudaGetSymbolAddress((void**)&xs,   g_xs);
    cudaGetSymbolAddress((void**)&bc,   g_bc);
    cudaGetSymbolAddress((void**)&hsp,  g_hs);
    cudaGetSymbolAddress((void**)&Atp,  g_At);
    cudaGetSymbolAddress((void**)&Wred, g_Wred);

    // tiny prep (independent of the main chain)
    prep_at  <<<16, 256>>>(dt, A, Atp);
    prep_wred<<<64, 256>>>(W_out, Wred);

    // 1) xr = x @ W_in^T + b_in        (8192 x 4096, K=1024)
    gemm_tn<128,128,8,8,8,false><<<dim3((2*DINN)/128, MROWS/128), 256>>>(
        x, DMOD, W_in, DMOD, b_in, xr, 2*DINN, DMOD, nullptr, nullptr);

    // 2) xs = silu(causal_dwconv(xi) + conv_b)
    conv_silu<<<(MROWS*DINN)/256, 256>>>(xr, conv_w, conv_b, xs);

    // 3) bc = xs @ W_x^T + b_x         (8192 x 32, K=2048)
    gemm_tn<128,32,16,8,4,false><<<dim3(1, MROWS/128), 128>>>(
        xs, DINN, W_x, DINN, b_x, bc, 32, DINN, nullptr, nullptr);

    // 4) sequential scan -> hs
    scan_kernel<<<BATCH, 16>>>(bc, Atp, hsp);

    // 5) out = res @ W_out^T + hs @ Wred^T + b_out   (8192 x 1024, K=2048)
    gemm_tn<128,128,8,8,8,true><<<dim3(DMOD/128, MROWS/128), 256>>>(
        xr + DINN, 2*DINN, W_out, DINN, b_out, out, DMOD, DINN, hsp, Wred);
}

// round 3
// speedup vs baseline: 2.3030x; 2.3030x over previous
#include <cuda_runtime.h>
#include <cuda_bf16.h>
#include <math.h>
#include <stdint.h>

#define BATCH 4
#define LSEQ  2048
#define DMOD  1024
#define DST   16
#define KCONV 4
#define DINN  2048
#define MROWS (BATCH*LSEQ)   /* 8192 */
#define KEXT  (DINN + 64)    /* 2112: res | hs | zero-pad */

// ---------------- scratch (device globals: allocation-free rule) ------------
__device__ __align__(128) float g_xi[(size_t)MROWS * DINN];
__device__ __align__(128) float g_xs[(size_t)MROWS * DINN];
__device__ __align__(128) float g_bc[(size_t)MROWS * 32];
__device__ __align__(128) float g_hs[(size_t)MROWS * DST];
__device__ __align__(128) float g_At[16*16*16];
__device__ __align__(128) float g_Wred[DMOD*DST];
__device__ __align__(128) __nv_bfloat16 g_xh[(size_t)MROWS*DMOD],   g_xl[(size_t)MROWS*DMOD];
__device__ __align__(128) __nv_bfloat16 g_winh[(size_t)(2*DINN)*DMOD], g_winl[(size_t)(2*DINN)*DMOD];
__device__ __align__(128) __nv_bfloat16 g_resh[(size_t)MROWS*KEXT], g_resl[(size_t)MROWS*KEXT];
__device__ __align__(128) __nv_bfloat16 g_woh[(size_t)DMOD*KEXT],  g_wol[(size_t)DMOD*KEXT];

// ============================ PTX helpers (arch-agnostic) ====================
__device__ __forceinline__ uint32_t smem_u32(const void* p) {
    uint32_t a;
    asm("{ .reg .u64 t; cvta.to.shared.u64 t, %1; cvt.u32.u64 %0, t; }"
        : "=r"(a) : "l"(p));
    return a;
}
__device__ __forceinline__ void cp16(uint32_t s, const void* g) {
    asm volatile("cp.async.cg.shared.global [%0], [%1], 16;" :: "r"(s), "l"(g));
}
#define CP_COMMIT() asm volatile("cp.async.commit_group;" ::: "memory")
template<int N> __device__ __forceinline__ void cp_wait() {
    asm volatile("cp.async.wait_group %0;" :: "n"(N) : "memory");
}
__device__ __forceinline__ void ldsm_x4(uint32_t& r0, uint32_t& r1,
                                        uint32_t& r2, uint32_t& r3, uint32_t a) {
    asm volatile("ldmatrix.sync.aligned.m8n8.x4.shared.b16 {%0,%1,%2,%3}, [%4];"
                 : "=r"(r0), "=r"(r1), "=r"(r2), "=r"(r3) : "r"(a));
}
__device__ __forceinline__ void mma16816(float* c,
    uint32_t a0, uint32_t a1, uint32_t a2, uint32_t a3, uint32_t b0, uint32_t b1) {
    asm volatile(
        "mma.sync.aligned.m16n8k16.row.col.f32.bf16.bf16.f32 "
        "{%0,%1,%2,%3}, {%4,%5,%6,%7}, {%8,%9}, {%0,%1,%2,%3};"
        : "+f"(c[0]), "+f"(c[1]), "+f"(c[2]), "+f"(c[3])
        : "r"(a0), "r"(a1), "r"(a2), "r"(a3), "r"(b0), "r"(b1));
}
__device__ __forceinline__ uint32_t swz(uint32_t bo) { return bo ^ ((bo >> 3) & 0x70); }

// ================== split-bf16 GEMM via mma.sync: C = A @ B^T ================
// A: [M,K] bf16 hi/lo; B: [N,K] bf16 hi/lo. 128x128 CTA tile, BK=64 chunks,
// 3-stage cp.async pipeline. 3 passes: Ah*Bh + Ah*Bl + Al*Bh.
#define TILE_B   16384           /* 128 rows x 128 bytes */
#define STAGE_B  (4*TILE_B)      /* Ah,Al,Bh,Bl */
#define SMEM_NEED (3*STAGE_B + 1024)

__device__ __forceinline__ void load_tile_async(const __nv_bfloat16* __restrict__ g,
                                                long row0, int ld, int k0,
                                                uint32_t sb, int tid) {
    #pragma unroll
    for (int t = 0; t < 4; t++) {
        int idx = tid + t * 256;
        int r = idx >> 3, cv = idx & 7;
        cp16(sb + swz((uint32_t)(r * 128 + cv * 16)),
             g + (row0 + r) * (long)ld + k0 + cv * 8);
    }
}

template<int MODE>   // 0: GEMM1 (xi fp32 | res split-bf16), 1: plain fp32+bias
__global__ __launch_bounds__(256, 1)
void gemm_mma(const __nv_bfloat16* __restrict__ Ah, const __nv_bfloat16* __restrict__ Al, int lda,
              const __nv_bfloat16* __restrict__ Bh, const __nv_bfloat16* __restrict__ Bl, int ldb,
              const float* __restrict__ bias,
              float* __restrict__ Cout, int ldc,
              __nv_bfloat16* __restrict__ resh, __nv_bfloat16* __restrict__ resl, int ldr,
              int K)
{
    extern __shared__ char smem_raw[];
    uint32_t raw = smem_u32(smem_raw);
    const uint32_t sbase = (raw + 1023u) & ~1023u;

    const int tid  = threadIdx.x;
    const int wid  = tid >> 5, lane = tid & 31;
    const int warpM = wid & 3, warpN = wid >> 2;
    const long m0 = (long)blockIdx.y * 128;
    const int  n0 = blockIdx.x * 128;

    float acc[2][8][4];
    #pragma unroll
    for (int i = 0; i < 2; i++)
        #pragma unroll
        for (int j = 0; j < 8; j++)
            #pragma unroll
            for (int q = 0; q < 4; q++) acc[i][j][q] = 0.f;

    // per-lane ldmatrix row/kh (see fragment layout notes)
    const int rowA0 = warpM * 32 + (lane & 7) + ((lane >> 3) & 1) * 8;  // + mi*16
    const int khA   = (lane >> 4) & 1;
    const int rowB0 = warpN * 64 + (lane & 7) + ((lane >> 4) & 1) * 8;  // + nb*16
    const int khB   = (lane >> 3) & 1;

    const int NC = K / 64;

    auto issue = [&](int c) {
        uint32_t st = sbase + (uint32_t)(c % 3) * STAGE_B;
        int k0 = c * 64;
        load_tile_async(Ah, m0, lda, k0, st,             tid);
        load_tile_async(Al, m0, lda, k0, st + TILE_B,    tid);
        load_tile_async(Bh, n0, ldb, k0, st + 2*TILE_B,  tid);
        load_tile_async(Bl, n0, ldb, k0, st + 3*TILE_B,  tid);
        CP_COMMIT();
    };

    issue(0);
    if (NC > 1) issue(1);

    for (int c = 0; c < NC; c++) {
        if (c + 2 < NC)      { issue(c + 2); cp_wait<2>(); }
        else if (c + 1 < NC) { cp_wait<1>(); }
        else                 { cp_wait<0>(); }
        __syncthreads();

        uint32_t st = sbase + (uint32_t)(c % 3) * STAGE_B;
        #pragma unroll
        for (int ks = 0; ks < 4; ks++) {
            uint32_t ah[2][4], al[2][4], bh[8][2], bl[8][2];
            #pragma unroll
            for (int mi = 0; mi < 2; mi++) {
                uint32_t bo = swz((uint32_t)((rowA0 + mi*16) * 128 + ks*32 + khA*16));
                ldsm_x4(ah[mi][0], ah[mi][1], ah[mi][2], ah[mi][3], st + bo);
                ldsm_x4(al[mi][0], al[mi][1], al[mi][2], al[mi][3], st + TILE_B + bo);
            }
            #pragma unroll
            for (int nb = 0; nb < 4; nb++) {
                uint32_t bo = swz((uint32_t)((rowB0 + nb*16) * 128 + ks*32 + khB*16));
                ldsm_x4(bh[nb*2][0], bh[nb*2][1], bh[nb*2+1][0], bh[nb*2+1][1],
                        st + 2*TILE_B + bo);
                ldsm_x4(bl[nb*2][0], bl[nb*2][1], bl[nb*2+1][0], bl[nb*2+1][1],
                        st + 3*TILE_B + bo);
            }
            #pragma unroll
            for (int mi = 0; mi < 2; mi++)
                #pragma unroll
                for (int nf = 0; nf < 8; nf++)
                    mma16816(acc[mi][nf], ah[mi][0], ah[mi][1], ah[mi][2], ah[mi][3],
                             bh[nf][0], bh[nf][1]);
            #pragma unroll
            for (int mi = 0; mi < 2; mi++)
                #pragma unroll
                for (int nf = 0; nf < 8; nf++)
                    mma16816(acc[mi][nf], ah[mi][0], ah[mi][1], ah[mi][2], ah[mi][3],
                             bl[nf][0], bl[nf][1]);
            #pragma unroll
            for (int mi = 0; mi < 2; mi++)
                #pragma unroll
                for (int nf = 0; nf < 8; nf++)
                    mma16816(acc[mi][nf], al[mi][0], al[mi][1], al[mi][2], al[mi][3],
                             bh[nf][0], bh[nf][1]);
        }
        __syncthreads();
    }

    // epilogue from registers
    const int g  = lane >> 2, tg = lane & 3;
    #pragma unroll
    for (int mi = 0; mi < 2; mi++) {
        #pragma unroll
        for (int h = 0; h < 2; h++) {
            long m = m0 + warpM * 32 + mi * 16 + h * 8 + g;
            #pragma unroll
            for (int nf = 0; nf < 8; nf++) {
                int n = n0 + warpN * 64 + nf * 8 + tg * 2;
                float2 bv = *reinterpret_cast<const float2*>(&bias[n]);
                float v0 = acc[mi][nf][h*2+0] + bv.x;
                float v1 = acc[mi][nf][h*2+1] + bv.y;
                if (MODE == 0) {
                    if (n < DINN) {
                        *reinterpret_cast<float2*>(&Cout[m * (long)ldc + n]) =
                            make_float2(v0, v1);
                    } else {
                        __nv_bfloat16 h0 = __float2bfloat16(v0);
                        __nv_bfloat16 h1 = __float2bfloat16(v1);
                        __nv_bfloat16 l0 = __float2bfloat16(v0 - __bfloat162float(h0));
                        __nv_bfloat16 l1 = __float2bfloat16(v1 - __bfloat162float(h1));
                        long o = m * (long)ldr + (n - DINN);
                        __nv_bfloat162 ph; ph.x = h0; ph.y = h1;
                        __nv_bfloat162 pl; pl.x = l0; pl.y = l1;
                        *reinterpret_cast<__nv_bfloat162*>(&resh[o]) = ph;
                        *reinterpret_cast<__nv_bfloat162*>(&resl[o]) = pl;
                    }
                } else {
                    *reinterpret_cast<float2*>(&Cout[m * (long)ldc + n]) =
                        make_float2(v0, v1);
                }
            }
        }
    }
}

// ---------------- prep kernels -----------------------------------------------
__global__ void prep_at(const float* __restrict__ dt, const float* __restrict__ A,
                        float* __restrict__ At) {
    int t = blockIdx.x * blockDim.x + threadIdx.x;
    if (t < 4096) {
        int j = t >> 8, e = t & 255;
        At[t] = expf(expf(dt[j]) * A[e]);
    }
}

__global__ void prep_wred(const float* __restrict__ Wout, float* __restrict__ Wred) {
    int t = blockIdx.x * blockDim.x + threadIdx.x;
    if (t < DMOD * DST) {
        int m = t >> 4, s = t & 15;
        float sum = 0.f;
        #pragma unroll 8
        for (int r = 0; r < DINN / DST; r++)
            sum += Wout[(size_t)m * DINN + r * DST + s];
        Wred[t] = sum;
    }
}

__global__ void split_f32(const float* __restrict__ src,
                          __nv_bfloat16* __restrict__ hi,
                          __nv_bfloat16* __restrict__ lo, long n) {
    long t = (long)blockIdx.x * blockDim.x + threadIdx.x;
    if (t < n) {
        float v = src[t];
        __nv_bfloat16 h = __float2bfloat16(v);
        hi[t] = h;
        lo[t] = __float2bfloat16(v - __bfloat162float(h));
    }
}

__global__ void split_woutext(const float* __restrict__ Wout,
                              const float* __restrict__ Wred,
                              __nv_bfloat16* __restrict__ hi,
                              __nv_bfloat16* __restrict__ lo) {
    int t = blockIdx.x * blockDim.x + threadIdx.x;
    if (t < DMOD * KEXT) {
        int n = t / KEXT, k = t % KEXT;
        float v = (k < DINN) ? Wout[(size_t)n * DINN + k]
                 : (k < DINN + DST) ? Wred[n * DST + (k - DINN)] : 0.f;
        __nv_bfloat16 h = __float2bfloat16(v);
        hi[t] = h;
        lo[t] = __float2bfloat16(v - __bfloat162float(h));
    }
}

__global__ void fill_hs_ext(const float* __restrict__ hs,
                            __nv_bfloat16* __restrict__ resh,
                            __nv_bfloat16* __restrict__ resl) {
    int t = blockIdx.x * blockDim.x + threadIdx.x;
    if (t < MROWS * 64) {
        int m = t >> 6, j = t & 63;
        float v = (j < DST) ? hs[m * DST + j] : 0.f;
        __nv_bfloat16 h = __float2bfloat16(v);
        long o = (long)m * KEXT + DINN + j;
        resh[o] = h;
        resl[o] = __float2bfloat16(v - __bfloat162float(h));
    }
}

// ---------------- depthwise causal conv (K=4) + SiLU -------------------------
__global__ void conv_silu(const float* __restrict__ xi,
                          const float* __restrict__ w,
                          const float* __restrict__ cb,
                          float* __restrict__ xs)
{
    long t = (long)blockIdx.x * blockDim.x + threadIdx.x;
    if (t >= (long)MROWS * DINN) return;
    int  c  = (int)(t & (DINN - 1));
    long bl = t >> 11;
    int  l  = (int)(bl & (LSEQ - 1));
    long row0 = bl - l;

    float4 wv = *reinterpret_cast<const float4*>(&w[c * 4]);
    float acc = cb[c];
    const float wk[4] = {wv.x, wv.y, wv.z, wv.w};
    #pragma unroll
    for (int k = 0; k < KCONV; k++) {
        int ll = l - (KCONV - 1) + k;
        if (ll >= 0)
            acc = fmaf(xi[(size_t)(row0 + ll) * DINN + c], wk[k], acc);
    }
    float s = 1.f / (1.f + expf(-acc));
    xs[t] = acc * s;
}

// ---------------- SIMT SGEMM for the tiny B/C projection ---------------------
template<int BM,int BN,int BK,int TM,int TN>
__global__ __launch_bounds__((BM/TM)*(BN/TN))
void gemm_tn(const float* __restrict__ A, int lda,
             const float* __restrict__ B, int ldb,
             const float* __restrict__ bias,
             float* __restrict__ C, int ldc, int K)
{
    constexpr int THREADS = (BM/TM)*(BN/TN);
    __shared__ float As[BK][BM+4];
    __shared__ float Bs[BK][BN+4];
    const int tid = threadIdx.x;
    const int tx  = tid % (BN/TN);
    const int ty  = tid / (BN/TN);
    const int m0  = blockIdx.y * BM;
    const int n0  = blockIdx.x * BN;

    float acc[TM][TN];
    #pragma unroll
    for (int i = 0; i < TM; i++)
        #pragma unroll
        for (int j = 0; j < TN; j++) acc[i][j] = 0.f;

    for (int k0 = 0; k0 < K; k0 += BK) {
        for (int idx = tid; idx < BM*(BK/4); idx += THREADS) {
            int r = idx / (BK/4), cv = idx % (BK/4);
            float4 v = *reinterpret_cast<const float4*>(&A[(size_t)(m0+r)*lda + k0 + cv*4]);
            As[cv*4+0][r] = v.x; As[cv*4+1][r] = v.y;
            As[cv*4+2][r] = v.z; As[cv*4+3][r] = v.w;
        }
        for (int idx = tid; idx < BN*(BK/4); idx += THREADS) {
            int r = idx / (BK/4), cv = idx % (BK/4);
            float4 v = *reinterpret_cast<const float4*>(&B[(size_t)(n0+r)*ldb + k0 + cv*4]);
            Bs[cv*4+0][r] = v.x; Bs[cv*4+1][r] = v.y;
            Bs[cv*4+2][r] = v.z; Bs[cv*4+3][r] = v.w;
        }
        __syncthreads();
        #pragma unroll
        for (int k = 0; k < BK; k++) {
            float a[TM], bb[TN];
            #pragma unroll
            for (int i = 0; i < TM; i++) a[i]  = As[k][ty*TM + i];
            #pragma unroll
            for (int j = 0; j < TN; j++) bb[j] = Bs[k][tx*TN + j];
            #pragma unroll
            for (int i = 0; i < TM; i++)
                #pragma unroll
                for (int j = 0; j < TN; j++)
                    acc[i][j] = fmaf(a[i], bb[j], acc[i][j]);
        }
        __syncthreads();
    }
    #pragma unroll
    for (int i = 0; i < TM; i++) {
        int m = m0 + ty*TM + i;
        #pragma unroll
        for (int j = 0; j < TN; j++) {
            int n = n0 + tx*TN + j;
            C[(size_t)m*ldc + n] = acc[i][j] + bias[n];
        }
    }
}

// ---------------- sequential nonlinear scan ----------------------------------
__global__ void scan_kernel(const float* __restrict__ bc,
                            const float* __restrict__ At,
                            float* __restrict__ hs)
{
    const int b = blockIdx.x;
    const int i = threadIdx.x;            // 0..15
    const unsigned mask = 0xffffu;
    __shared__ float sAt[16*16*16];
    __shared__ float sBC[64*32];

    for (int t = i; t < 4096/4; t += 16)
        reinterpret_cast<float4*>(sAt)[t] = reinterpret_cast<const float4*>(At)[t];

    const float* bcb = bc + (size_t)b*LSEQ*32;
    float*       hsb = hs + (size_t)b*LSEQ*DST;
    float h = 0.f;

    for (int l0 = 0; l0 < LSEQ; l0 += 64) {
        __syncwarp(mask);
        const float4* src = reinterpret_cast<const float4*>(bcb + (size_t)l0*32);
        for (int t = i; t < 64*32/4; t += 16)
            reinterpret_cast<float4*>(sBC)[t] = src[t];
        __syncwarp(mask);
        for (int ll = 0; ll < 64; ll++) {
            int l = l0 + ll;
            float Bv = sBC[ll*32 + i];
            float Cv = sBC[ll*32 + 16 + i];
            const float* Ar = &sAt[((l & 15) << 8) + (i << 4)];
            float a0 = Cv, a1 = 0.f, a2 = 0.f, a3 = Bv * h;
            #pragma unroll
            for (int j = 0; j < 16; j += 4) {
                a0 = fmaf(Ar[j+0], __shfl_sync(mask, h, j+0), a0);
                a1 = fmaf(Ar[j+1], __shfl_sync(mask, h, j+1), a1);
                a2 = fmaf(Ar[j+2], __shfl_sync(mask, h, j+2), a2);
                a3 = fmaf(Ar[j+3], __shfl_sync(mask, h, j+3), a3);
            }
            h = tanhf((a0 + a1) + (a2 + a3));
            hsb[(size_t)l*DST + i] = h;
        }
    }
}

// ---------------- launcher ----------------------------------------------------
extern "C" void kernel_launch(void* const* d_in, const int* in_sizes, int n_in,
                              void* d_out, int out_size)
{
    const float* x      = (const float*)d_in[0];
    const float* W_in   = (const float*)d_in[1];
    const float* b_in   = (const float*)d_in[2];
    const float* conv_w = (const float*)d_in[3];
    const float* conv_b = (const float*)d_in[4];
    const float* W_x    = (const float*)d_in[5];
    const float* b_x    = (const float*)d_in[6];
    const float* dt     = (const float*)d_in[7];
    const float* A      = (const float*)d_in[8];
    const float* W_out  = (const float*)d_in[10];
    const float* b_out  = (const float*)d_in[11];
    float* out = (float*)d_out;

    float *xi, *xs, *bc, *hsp, *Atp, *Wred;
    __nv_bfloat16 *xh, *xl, *winh, *winl, *resh, *resl, *woh, *wol;
    cudaGetSymbolAddress((void**)&xi,   g_xi);
    cudaGetSymbolAddress((void**)&xs,   g_xs);
    cudaGetSymbolAddress((void**)&bc,   g_bc);
    cudaGetSymbolAddress((void**)&hsp,  g_hs);
    cudaGetSymbolAddress((void**)&Atp,  g_At);
    cudaGetSymbolAddress((void**)&Wred, g_Wred);
    cudaGetSymbolAddress((void**)&xh,   g_xh);
    cudaGetSymbolAddress((void**)&xl,   g_xl);
    cudaGetSymbolAddress((void**)&winh, g_winh);
    cudaGetSymbolAddress((void**)&winl, g_winl);
    cudaGetSymbolAddress((void**)&resh, g_resh);
    cudaGetSymbolAddress((void**)&resl, g_resl);
    cudaGetSymbolAddress((void**)&woh,  g_woh);
    cudaGetSymbolAddress((void**)&wol,  g_wol);

    cudaFuncSetAttribute(gemm_mma<0>, cudaFuncAttributeMaxDynamicSharedMemorySize, SMEM_NEED);
    cudaFuncSetAttribute(gemm_mma<1>, cudaFuncAttributeMaxDynamicSharedMemorySize, SMEM_NEED);

    // preps + operand splits
    prep_at  <<<16, 256>>>(dt, A, Atp);
    prep_wred<<<64, 256>>>(W_out, Wred);
    split_woutext<<<(DMOD*KEXT + 255)/256, 256>>>(W_out, Wred, woh, wol);
    split_f32<<<(int)(((long)MROWS*DMOD + 255)/256), 256>>>(x, xh, xl, (long)MROWS*DMOD);
    split_f32<<<(int)(((long)(2*DINN)*DMOD + 255)/256), 256>>>(W_in, winh, winl, (long)(2*DINN)*DMOD);

    // 1) in_proj (mma.sync): xi fp32 + res bf16-split
    gemm_mma<0><<<dim3((2*DINN)/128, MROWS/128), 256, SMEM_NEED>>>(
        xh, xl, DMOD, winh, winl, DMOD, b_in,
        xi, DINN, resh, resl, KEXT, DMOD);

    // 2) conv + silu
    conv_silu<<<(MROWS*DINN)/256, 256>>>(xi, conv_w, conv_b, xs);

    // 3) bc = xs @ W_x^T + b_x (small SIMT GEMM)
    gemm_tn<128,32,16,8,4><<<dim3(1, MROWS/128), 128>>>(
        xs, DINN, W_x, DINN, b_x, bc, 32, DINN);

    // 4) scan -> hs, then append (split) hs columns
    scan_kernel<<<BATCH, 16>>>(bc, Atp, hsp);
    fill_hs_ext<<<(MROWS*64 + 255)/256, 256>>>(hsp, resh, resl);

    // 5) out = [res|hs] @ [W_out|Wred]^T + b_out (mma.sync)
    gemm_mma<1><<<dim3(DMOD/128, MROWS/128), 256, SMEM_NEED>>>(
        resh, resl, KEXT, woh, wol, KEXT, b_out,
        out, DMOD, nullptr, nullptr, KEXT, KEXT);
}

// round 4
// speedup vs baseline: 3.4225x; 1.4861x over previous
#include <cuda_runtime.h>
#include <cuda_bf16.h>
#include <math.h>
#include <stdint.h>

#define BATCH 4
#define LSEQ  2048
#define DMOD  1024
#define DST   16
#define KCONV 4
#define DINN  2048
#define MROWS (BATCH*LSEQ)   /* 8192 */
#define KEXT  (DINN + 64)    /* 2112: res | hs | zero-pad */

// ---------------- scratch (device globals) -----------------------------------
__device__ __align__(128) __nv_bfloat16 g_xib[(size_t)MROWS * DINN];  // xi bf16
__device__ __align__(128) __nv_bfloat16 g_xsb[(size_t)MROWS * DINN];  // silu(conv) bf16
__device__ __align__(128) float g_bc[(size_t)MROWS * 32];
__device__ __align__(128) float g_hs[(size_t)MROWS * DST];
__device__ __align__(128) float g_At[16*16*16];
__device__ __align__(128) float g_Wred[DMOD*DST];
__device__ __align__(128) __nv_bfloat16 g_xh[(size_t)MROWS*DMOD],   g_xl[(size_t)MROWS*DMOD];
__device__ __align__(128) __nv_bfloat16 g_winh[(size_t)(2*DINN)*DMOD], g_winl[(size_t)(2*DINN)*DMOD];
__device__ __align__(128) __nv_bfloat16 g_resh[(size_t)MROWS*KEXT], g_resl[(size_t)MROWS*KEXT];
__device__ __align__(128) __nv_bfloat16 g_woh[(size_t)DMOD*KEXT],  g_wol[(size_t)DMOD*KEXT];
__device__ __align__(128) __nv_bfloat16 g_wxh[(size_t)128*DINN];      // W_x padded to 128 rows

// ============================ PTX helpers (arch-agnostic) ====================
__device__ __forceinline__ uint32_t smem_u32(const void* p) {
    uint32_t a;
    asm("{ .reg .u64 t; cvta.to.shared.u64 t, %1; cvt.u32.u64 %0, t; }"
        : "=r"(a) : "l"(p));
    return a;
}
__device__ __forceinline__ void cp16(uint32_t s, const void* g) {
    asm volatile("cp.async.cg.shared.global [%0], [%1], 16;" :: "r"(s), "l"(g));
}
#define CP_COMMIT() asm volatile("cp.async.commit_group;" ::: "memory")
template<int N> __device__ __forceinline__ void cp_wait() {
    asm volatile("cp.async.wait_group %0;" :: "n"(N) : "memory");
}
__device__ __forceinline__ void ldsm_x4(uint32_t& r0, uint32_t& r1,
                                        uint32_t& r2, uint32_t& r3, uint32_t a) {
    asm volatile("ldmatrix.sync.aligned.m8n8.x4.shared.b16 {%0,%1,%2,%3}, [%4];"
                 : "=r"(r0), "=r"(r1), "=r"(r2), "=r"(r3) : "r"(a));
}
__device__ __forceinline__ void mma16816(float* c,
    uint32_t a0, uint32_t a1, uint32_t a2, uint32_t a3, uint32_t b0, uint32_t b1) {
    asm volatile(
        "mma.sync.aligned.m16n8k16.row.col.f32.bf16.bf16.f32 "
        "{%0,%1,%2,%3}, {%4,%5,%6,%7}, {%8,%9}, {%0,%1,%2,%3};"
        : "+f"(c[0]), "+f"(c[1]), "+f"(c[2]), "+f"(c[3])
        : "r"(a0), "r"(a1), "r"(a2), "r"(a3), "r"(b0), "r"(b1));
}
__device__ __forceinline__ uint32_t swz(uint32_t bo) { return bo ^ ((bo >> 3) & 0x70); }

// ================== split-bf16 GEMM via mma.sync: C = A @ B^T ================
// MODE 0: res split-bf16 out (resh/resl)    MODE 1: fp32 + bias
// MODE 2: bf16 + bias (xi)                  MODE 3: fp32 + bias, n<32 only (bc)
// PASSES: 1 (Ah*Bh) or 3 (Ah*Bh + Ah*Bl + Al*Bh)
template<int ROWS>
__device__ __forceinline__ void load_tile_async(const __nv_bfloat16* __restrict__ g,
                                                long row0, int ld, int k0,
                                                uint32_t sb, int tid) {
    #pragma unroll
    for (int t = 0; t < ROWS/32; t++) {
        int idx = tid + t * 256;
        int r = idx >> 3, cv = idx & 7;
        cp16(sb + swz((uint32_t)(r * 128 + cv * 16)),
             g + (row0 + r) * (long)ld + k0 + cv * 8);
    }
}

template<int MODE, int PASSES, int BN_>
__global__ __launch_bounds__(256, 1)
void gemm_mma(const __nv_bfloat16* __restrict__ Ah, const __nv_bfloat16* __restrict__ Al, int lda,
              const __nv_bfloat16* __restrict__ Bh, const __nv_bfloat16* __restrict__ Bl, int ldb,
              const float* __restrict__ bias,
              float* __restrict__ Cout, int ldc,
              __nv_bfloat16* __restrict__ outh, __nv_bfloat16* __restrict__ outl, int ldr,
              int K)
{
    constexpr int ATILE = 16384;            // 128 x 128B
    constexpr int BTILE = BN_ * 128;
    constexpr int OFF_AL = ATILE;
    constexpr int OFF_BH = (PASSES == 3) ? 2*ATILE : ATILE;
    constexpr int OFF_BL = OFF_BH + BTILE;
    constexpr int STAGE  = OFF_BH + ((PASSES == 3) ? 2*BTILE : BTILE);
    constexpr int NF = BN_ / 16;            // n-fragments per warp
    constexpr int NB = BN_ / 32;            // ldsm_x4 B loads per warp per ks

    extern __shared__ char smem_raw[];
    uint32_t raw = smem_u32(smem_raw);
    const uint32_t sbase = (raw + 1023u) & ~1023u;

    const int tid  = threadIdx.x;
    const int wid  = tid >> 5, lane = tid & 31;
    const int warpM = wid & 3, warpN = wid >> 2;
    const long m0 = (long)blockIdx.y * 128;
    const int  n0 = blockIdx.x * BN_;

    float acc[2][NF][4];
    #pragma unroll
    for (int i = 0; i < 2; i++)
        #pragma unroll
        for (int j = 0; j < NF; j++)
            #pragma unroll
            for (int q = 0; q < 4; q++) acc[i][j][q] = 0.f;

    const int rowA0 = warpM * 32 + (lane & 7) + ((lane >> 3) & 1) * 8;
    const int khA   = (lane >> 4) & 1;
    const int rowB0 = warpN * (BN_/2) + (lane & 7) + ((lane >> 4) & 1) * 8;
    const int khB   = (lane >> 3) & 1;

    const int NC = K / 64;

    auto issue = [&](int c) {
        uint32_t st = sbase + (uint32_t)(c % 3) * STAGE;
        int k0 = c * 64;
        load_tile_async<128>(Ah, m0, lda, k0, st, tid);
        load_tile_async<BN_>(Bh, n0, ldb, k0, st + OFF_BH, tid);
        if (PASSES == 3) {
            load_tile_async<128>(Al, m0, lda, k0, st + OFF_AL, tid);
            load_tile_async<BN_>(Bl, n0, ldb, k0, st + OFF_BL, tid);
        }
        CP_COMMIT();
    };

    issue(0);
    if (NC > 1) issue(1);

    for (int c = 0; c < NC; c++) {
        if (c + 2 < NC)      { issue(c + 2); cp_wait<2>(); }
        else if (c + 1 < NC) { cp_wait<1>(); }
        else                 { cp_wait<0>(); }
        __syncthreads();

        uint32_t st = sbase + (uint32_t)(c % 3) * STAGE;
        #pragma unroll
        for (int ks = 0; ks < 4; ks++) {
            uint32_t ah[2][4], al[2][4], bh[NF][2], bl[NF][2];
            #pragma unroll
            for (int mi = 0; mi < 2; mi++) {
                uint32_t bo = swz((uint32_t)((rowA0 + mi*16) * 128 + ks*32 + khA*16));
                ldsm_x4(ah[mi][0], ah[mi][1], ah[mi][2], ah[mi][3], st + bo);
                if (PASSES == 3)
                    ldsm_x4(al[mi][0], al[mi][1], al[mi][2], al[mi][3], st + OFF_AL + bo);
            }
            #pragma unroll
            for (int nb = 0; nb < NB; nb++) {
                uint32_t bo = swz((uint32_t)((rowB0 + nb*16) * 128 + ks*32 + khB*16));
                ldsm_x4(bh[nb*2][0], bh[nb*2][1], bh[nb*2+1][0], bh[nb*2+1][1],
                        st + OFF_BH + bo);
                if (PASSES == 3)
                    ldsm_x4(bl[nb*2][0], bl[nb*2][1], bl[nb*2+1][0], bl[nb*2+1][1],
                            st + OFF_BL + bo);
            }
            #pragma unroll
            for (int mi = 0; mi < 2; mi++)
                #pragma unroll
                for (int nf = 0; nf < NF; nf++)
                    mma16816(acc[mi][nf], ah[mi][0], ah[mi][1], ah[mi][2], ah[mi][3],
                             bh[nf][0], bh[nf][1]);
            if (PASSES == 3) {
                #pragma unroll
                for (int mi = 0; mi < 2; mi++)
                    #pragma unroll
                    for (int nf = 0; nf < NF; nf++)
                        mma16816(acc[mi][nf], ah[mi][0], ah[mi][1], ah[mi][2], ah[mi][3],
                                 bl[nf][0], bl[nf][1]);
                #pragma unroll
                for (int mi = 0; mi < 2; mi++)
                    #pragma unroll
                    for (int nf = 0; nf < NF; nf++)
                        mma16816(acc[mi][nf], al[mi][0], al[mi][1], al[mi][2], al[mi][3],
                                 bh[nf][0], bh[nf][1]);
            }
        }
        __syncthreads();
    }

    // epilogue from registers
    const int g  = lane >> 2, tg = lane & 3;
    #pragma unroll
    for (int mi = 0; mi < 2; mi++) {
        #pragma unroll
        for (int h = 0; h < 2; h++) {
            long m = m0 + warpM * 32 + mi * 16 + h * 8 + g;
            #pragma unroll
            for (int nf = 0; nf < NF; nf++) {
                int n = n0 + warpN * (BN_/2) + nf * 8 + tg * 2;
                if (MODE == 3 && n >= 32) continue;
                float2 bv = *reinterpret_cast<const float2*>(&bias[n]);
                float v0 = acc[mi][nf][h*2+0] + bv.x;
                float v1 = acc[mi][nf][h*2+1] + bv.y;
                if (MODE == 0) {
                    __nv_bfloat16 h0 = __float2bfloat16(v0);
                    __nv_bfloat16 h1 = __float2bfloat16(v1);
                    __nv_bfloat16 l0 = __float2bfloat16(v0 - __bfloat162float(h0));
                    __nv_bfloat16 l1 = __float2bfloat16(v1 - __bfloat162float(h1));
                    long o = m * (long)ldr + n;
                    __nv_bfloat162 ph; ph.x = h0; ph.y = h1;
                    __nv_bfloat162 pl; pl.x = l0; pl.y = l1;
                    *reinterpret_cast<__nv_bfloat162*>(&outh[o]) = ph;
                    *reinterpret_cast<__nv_bfloat162*>(&outl[o]) = pl;
                } else if (MODE == 2) {
                    __nv_bfloat162 p;
                    p.x = __float2bfloat16(v0);
                    p.y = __float2bfloat16(v1);
                    *reinterpret_cast<__nv_bfloat162*>(&outh[m * (long)ldr + n]) = p;
                } else {
                    *reinterpret_cast<float2*>(&Cout[m * (long)ldc + n]) =
                        make_float2(v0, v1);
                }
            }
        }
    }
}

// ---------------- prep kernels -----------------------------------------------
__global__ void prep_at(const float* __restrict__ dt, const float* __restrict__ A,
                        float* __restrict__ At) {
    int t = blockIdx.x * blockDim.x + threadIdx.x;
    if (t < 4096) {
        int j = t >> 8, e = t & 255;
        At[t] = expf(expf(dt[j]) * A[e]);
    }
}

__global__ void prep_wred(const float* __restrict__ Wout, float* __restrict__ Wred) {
    int t = blockIdx.x * blockDim.x + threadIdx.x;
    if (t < DMOD * DST) {
        int m = t >> 4, s = t & 15;
        float sum = 0.f;
        #pragma unroll 8
        for (int r = 0; r < DINN / DST; r++)
            sum += Wout[(size_t)m * DINN + r * DST + s];
        Wred[t] = sum;
    }
}

// vectorized fp32 -> bf16 hi/lo split (n divisible by 4)
__global__ void split_f32_v4(const float* __restrict__ src,
                             __nv_bfloat16* __restrict__ hi,
                             __nv_bfloat16* __restrict__ lo, long n4) {
    long t = (long)blockIdx.x * blockDim.x + threadIdx.x;
    if (t < n4) {
        float4 v = reinterpret_cast<const float4*>(src)[t];
        __nv_bfloat16 h0 = __float2bfloat16(v.x), h1 = __float2bfloat16(v.y);
        __nv_bfloat16 h2 = __float2bfloat16(v.z), h3 = __float2bfloat16(v.w);
        __nv_bfloat162 ha; ha.x = h0; ha.y = h1;
        __nv_bfloat162 hb; hb.x = h2; hb.y = h3;
        __nv_bfloat162 la, lb;
        la.x = __float2bfloat16(v.x - __bfloat162float(h0));
        la.y = __float2bfloat16(v.y - __bfloat162float(h1));
        lb.x = __float2bfloat16(v.z - __bfloat162float(h2));
        lb.y = __float2bfloat16(v.w - __bfloat162float(h3));
        reinterpret_cast<__nv_bfloat162*>(hi)[t*2]   = ha;
        reinterpret_cast<__nv_bfloat162*>(hi)[t*2+1] = hb;
        reinterpret_cast<__nv_bfloat162*>(lo)[t*2]   = la;
        reinterpret_cast<__nv_bfloat162*>(lo)[t*2+1] = lb;
    }
}

// W_out_ext = [W_out | Wred | 0] (1024 x 2112), split
__global__ void split_woutext(const float* __restrict__ Wout,
                              const float* __restrict__ Wred,
                              __nv_bfloat16* __restrict__ hi,
                              __nv_bfloat16* __restrict__ lo) {
    int t = blockIdx.x * blockDim.x + threadIdx.x;
    if (t < DMOD * KEXT) {
        int n = t / KEXT, k = t % KEXT;
        float v = (k < DINN) ? Wout[(size_t)n * DINN + k]
                 : (k < DINN + DST) ? Wred[n * DST + (k - DINN)] : 0.f;
        __nv_bfloat16 h = __float2bfloat16(v);
        hi[t] = h;
        lo[t] = __float2bfloat16(v - __bfloat162float(h));
    }
}

// W_x padded to 128 rows, bf16 hi only
__global__ void prep_wx(const float* __restrict__ Wx, __nv_bfloat16* __restrict__ o) {
    int t = blockIdx.x * blockDim.x + threadIdx.x;
    if (t < 128 * DINN) {
        int n = t / DINN, k = t % DINN;
        o[t] = __float2bfloat16((n < 32) ? Wx[(size_t)n * DINN + k] : 0.f);
    }
}

// res_ext cols [2048,2112): hs (split) then zero pad
__global__ void fill_hs_ext(const float* __restrict__ hs,
                            __nv_bfloat16* __restrict__ resh,
                            __nv_bfloat16* __restrict__ resl) {
    int t = blockIdx.x * blockDim.x + threadIdx.x;
    if (t < MROWS * 64) {
        int m = t >> 6, j = t & 63;
        float v = (j < DST) ? hs[m * DST + j] : 0.f;
        __nv_bfloat16 h = __float2bfloat16(v);
        long o = (long)m * KEXT + DINN + j;
        resh[o] = h;
        resl[o] = __float2bfloat16(v - __bfloat162float(h));
    }
}

// ---------------- depthwise causal conv (K=4) + SiLU, bf16 in/out ------------
__global__ void conv_silu(const __nv_bfloat16* __restrict__ xi,
                          const float* __restrict__ w,
                          const float* __restrict__ cb,
                          __nv_bfloat16* __restrict__ xs)
{
    long t = (long)blockIdx.x * blockDim.x + threadIdx.x;
    if (t >= (long)MROWS * DINN) return;
    int  c  = (int)(t & (DINN - 1));
    long bl = t >> 11;
    int  l  = (int)(bl & (LSEQ - 1));
    long row0 = bl - l;

    float4 wv = *reinterpret_cast<const float4*>(&w[c * 4]);
    float acc = cb[c];
    const float wk[4] = {wv.x, wv.y, wv.z, wv.w};
    #pragma unroll
    for (int k = 0; k < KCONV; k++) {
        int ll = l - (KCONV - 1) + k;
        if (ll >= 0)
            acc = fmaf(__bfloat162float(xi[(size_t)(row0 + ll) * DINN + c]), wk[k], acc);
    }
    float s = 1.f / (1.f + expf(-acc));
    xs[t] = __float2bfloat16(acc * s);
}

// ---------------- sequential nonlinear scan ----------------------------------
__global__ void scan_kernel(const float* __restrict__ bc,
                            const float* __restrict__ At,
                            float* __restrict__ hs)
{
    const int b = blockIdx.x;
    const int i = threadIdx.x;            // 0..15
    const unsigned mask = 0xffffu;
    __shared__ float sAt[16*16*16];
    __shared__ float sBC[64*32];

    for (int t = i; t < 4096/4; t += 16)
        reinterpret_cast<float4*>(sAt)[t] = reinterpret_cast<const float4*>(At)[t];

    const float* bcb = bc + (size_t)b*LSEQ*32;
    float*       hsb = hs + (size_t)b*LSEQ*DST;
    float h = 0.f;

    for (int l0 = 0; l0 < LSEQ; l0 += 64) {
        __syncwarp(mask);
        const float4* src = reinterpret_cast<const float4*>(bcb + (size_t)l0*32);
        for (int t = i; t < 64*32/4; t += 16)
            reinterpret_cast<float4*>(sBC)[t] = src[t];
        __syncwarp(mask);
        for (int ll = 0; ll < 64; ll++) {
            int l = l0 + ll;
            float Bv = sBC[ll*32 + i];
            float Cv = sBC[ll*32 + 16 + i];
            const float* Ar = &sAt[((l & 15) << 8) + (i << 4)];
            float a0 = Cv, a1 = 0.f, a2 = 0.f, a3 = Bv * h;
            #pragma unroll
            for (int j = 0; j < 16; j += 4) {
                a0 = fmaf(Ar[j+0], __shfl_sync(mask, h, j+0), a0);
                a1 = fmaf(Ar[j+1], __shfl_sync(mask, h, j+1), a1);
                a2 = fmaf(Ar[j+2], __shfl_sync(mask, h, j+2), a2);
                a3 = fmaf(Ar[j+3], __shfl_sync(mask, h, j+3), a3);
            }
            h = tanhf((a0 + a1) + (a2 + a3));
            hsb[(size_t)l*DST + i] = h;
        }
    }
}

// ---------------- launcher ----------------------------------------------------
extern "C" void kernel_launch(void* const* d_in, const int* in_sizes, int n_in,
                              void* d_out, int out_size)
{
    const float* x      = (const float*)d_in[0];
    const float* W_in   = (const float*)d_in[1];
    const float* b_in   = (const float*)d_in[2];
    const float* conv_w = (const float*)d_in[3];
    const float* conv_b = (const float*)d_in[4];
    const float* W_x    = (const float*)d_in[5];
    const float* b_x    = (const float*)d_in[6];
    const float* dt     = (const float*)d_in[7];
    const float* A      = (const float*)d_in[8];
    const float* W_out  = (const float*)d_in[10];
    const float* b_out  = (const float*)d_in[11];
    float* out = (float*)d_out;

    float *bc, *hsp, *Atp, *Wred;
    __nv_bfloat16 *xib, *xsb, *xh, *xl, *winh, *winl, *resh, *resl, *woh, *wol, *wxh;
    cudaGetSymbolAddress((void**)&xib,  g_xib);
    cudaGetSymbolAddress((void**)&xsb,  g_xsb);
    cudaGetSymbolAddress((void**)&bc,   g_bc);
    cudaGetSymbolAddress((void**)&hsp,  g_hs);
    cudaGetSymbolAddress((void**)&Atp,  g_At);
    cudaGetSymbolAddress((void**)&Wred, g_Wred);
    cudaGetSymbolAddress((void**)&xh,   g_xh);
    cudaGetSymbolAddress((void**)&xl,   g_xl);
    cudaGetSymbolAddress((void**)&winh, g_winh);
    cudaGetSymbolAddress((void**)&winl, g_winl);
    cudaGetSymbolAddress((void**)&resh, g_resh);
    cudaGetSymbolAddress((void**)&resl, g_resl);
    cudaGetSymbolAddress((void**)&woh,  g_woh);
    cudaGetSymbolAddress((void**)&wol,  g_wol);
    cudaGetSymbolAddress((void**)&wxh,  g_wxh);

    // dynamic smem per instantiation: 3*STAGE + 1024
    const int SM_RES = 3 * (4 * 16384) + 1024;            // MODE0 P3 BN128: 192K+1K
    const int SM_XI  = 3 * (2 * 16384) + 1024;            // MODE2 P1 BN128: 96K+1K
    const int SM_BC  = 3 * (16384 + 64*128) + 1024;       // MODE3 P1 BN64:  72K+1K
    const int SM_OUT = 3 * (2 * 16384 + 2 * 64*128) + 1024; // MODE1 P3 BN64: 144K+1K
    cudaFuncSetAttribute(gemm_mma<0,3,128>, cudaFuncAttributeMaxDynamicSharedMemorySize, SM_RES);
    cudaFuncSetAttribute(gemm_mma<2,1,128>, cudaFuncAttributeMaxDynamicSharedMemorySize, SM_XI);
    cudaFuncSetAttribute(gemm_mma<3,1,64>,  cudaFuncAttributeMaxDynamicSharedMemorySize, SM_BC);
    cudaFuncSetAttribute(gemm_mma<1,3,64>,  cudaFuncAttributeMaxDynamicSharedMemorySize, SM_OUT);

    // preps + operand splits
    prep_at  <<<16, 256>>>(dt, A, Atp);
    prep_wred<<<64, 256>>>(W_out, Wred);
    split_woutext<<<(DMOD*KEXT + 255)/256, 256>>>(W_out, Wred, woh, wol);
    prep_wx<<<(128*DINN + 255)/256, 256>>>(W_x, wxh);
    split_f32_v4<<<(int)(((long)MROWS*DMOD/4 + 255)/256), 256>>>(x, xh, xl, (long)MROWS*DMOD/4);
    split_f32_v4<<<(int)(((long)(2*DINN)*DMOD/4 + 255)/256), 256>>>(W_in, winh, winl, (long)(2*DINN)*DMOD/4);

    // 1a) xi half: single-pass bf16 -> xi bf16
    gemm_mma<2,1,128><<<dim3(DINN/128, MROWS/128), 256, SM_XI>>>(
        xh, nullptr, DMOD, winh, nullptr, DMOD, b_in,
        nullptr, 0, xib, nullptr, DINN, DMOD);

    // 1b) res half: 3-pass -> split-bf16 res (cols 0..2047 of res_ext)
    gemm_mma<0,3,128><<<dim3(DINN/128, MROWS/128), 256, SM_RES>>>(
        xh, xl, DMOD, winh + (size_t)DINN*DMOD, winl + (size_t)DINN*DMOD, DMOD, b_in + DINN,
        nullptr, 0, resh, resl, KEXT, DMOD);

    // 2) conv + silu (bf16 in/out)
    conv_silu<<<(MROWS*DINN)/256, 256>>>(xib, conv_w, conv_b, xsb);

    // 3) bc = xs @ W_x^T + b_x (1-pass mma, padded N)
    gemm_mma<3,1,64><<<dim3(1, MROWS/128), 256, SM_BC>>>(
        xsb, nullptr, DINN, wxh, nullptr, DINN, b_x,
        bc, 32, nullptr, nullptr, 0, DINN);

    // 4) scan -> hs, then append split hs columns
    scan_kernel<<<BATCH, 16>>>(bc, Atp, hsp);
    fill_hs_ext<<<(MROWS*64 + 255)/256, 256>>>(hsp, resh, resl);

    // 5) out = [res|hs] @ [W_out|Wred]^T + b_out (3-pass, 128x64 tiles)
    gemm_mma<1,3,64><<<dim3(DMOD/64, MROWS/128), 256, SM_OUT>>>(
        resh, resl, KEXT, woh, wol, KEXT, b_out,
        out, DMOD, nullptr, nullptr, 0, KEXT);
}